// round 17
// baseline (speedup 1.0000x reference)
#include <cuda_runtime.h>
#include <cuda_bf16.h>
#include <math.h>
#include <stdint.h>

#define N_TOK 8192
#define C_DIM 1024
#define D_DIM 1024
#define E_NUM 8
#define SLOTS (N_TOK * 2)

#define BM 128
#define BN 128
#define BK 16
#define KTOT 1024
#define NCHUNK (KTOT / BK)   // 64

#define ASTR 24    // A smem row stride in bf16 (48B)
#define BSTR 136   // B smem row stride in bf16 (272B)
#define A_STAGE_B (BM * ASTR * 2)   // 6144 bytes per A stage
#define B_STAGE_B (BK * BSTR * 2)   // 4352 bytes per B stage

// ---------------- device scratch (NEVER passed as kernel args from host) ----------------
__device__ int   g_counts[E_NUM];
__device__ int   g_base[E_NUM];
__device__ int   g_cursor[E_NUM];
__device__ int   g_tok_e[SLOTS];
__device__ float g_tok_p[SLOTS];
__device__ int   g_slot_tok[SLOTS];
__device__ float g_slot_p[SLOTS];

__device__ __nv_bfloat16 g_xh[(size_t)N_TOK * C_DIM];
__device__ __nv_bfloat16 g_xl[(size_t)N_TOK * C_DIM];
__device__ __nv_bfloat16 g_w1h[(size_t)E_NUM * C_DIM * D_DIM];
__device__ __nv_bfloat16 g_w1l[(size_t)E_NUM * C_DIM * D_DIM];
__device__ __nv_bfloat16 g_w2h[(size_t)E_NUM * D_DIM * C_DIM];
__device__ __nv_bfloat16 g_w2l[(size_t)E_NUM * D_DIM * C_DIM];
__device__ __nv_bfloat16 g_hh[(size_t)(SLOTS + BM) * D_DIM];
__device__ __nv_bfloat16 g_hl[(size_t)(SLOTS + BM) * D_DIM];

// ---------------- helpers ----------------
__device__ __forceinline__ void mma_bf16(float* d, const uint32_t* a, const uint32_t* b) {
    asm volatile(
        "mma.sync.aligned.m16n8k16.row.col.f32.bf16.bf16.f32 "
        "{%0,%1,%2,%3}, {%4,%5,%6,%7}, {%8,%9}, {%0,%1,%2,%3};"
        : "+f"(d[0]), "+f"(d[1]), "+f"(d[2]), "+f"(d[3])
        : "r"(a[0]), "r"(a[1]), "r"(a[2]), "r"(a[3]), "r"(b[0]), "r"(b[1]));
}
__device__ __forceinline__ void ldsm_x4(uint32_t* r, uint32_t addr) {
    asm volatile("ldmatrix.sync.aligned.m8n8.x4.shared.b16 {%0,%1,%2,%3}, [%4];"
                 : "=r"(r[0]), "=r"(r[1]), "=r"(r[2]), "=r"(r[3]) : "r"(addr));
}
__device__ __forceinline__ void ldsm_x2t(uint32_t* r, uint32_t addr) {
    asm volatile("ldmatrix.sync.aligned.m8n8.x2.trans.shared.b16 {%0,%1}, [%2];"
                 : "=r"(r[0]), "=r"(r[1]) : "r"(addr));
}
__device__ __forceinline__ void split2(float v, __nv_bfloat16& h, __nv_bfloat16& l) {
    h = __float2bfloat16_rn(v);
    l = __float2bfloat16_rn(v - __bfloat162float(h));
}
__device__ __forceinline__ void cpa16(uint32_t s, const void* g) {
    asm volatile("cp.async.cg.shared.global [%0], [%1], 16;" :: "r"(s), "l"(g));
}
__device__ __forceinline__ void cp_commit() {
    asm volatile("cp.async.commit_group;" ::: "memory");
}
__device__ __forceinline__ void cp_wait0() {
    asm volatile("cp.async.wait_group 0;" ::: "memory");
}

// ---------------- small kernels (proven) ----------------
__global__ void init_kernel() {
    int t = threadIdx.x;
    if (t < E_NUM) g_counts[t] = 0;
}

__global__ void router_kernel(const float* __restrict__ x,
                              const float* __restrict__ rw) {
    __shared__ float srw[E_NUM * C_DIM];
    int tid = threadIdx.x;
    for (int i = tid; i < E_NUM * C_DIM; i += 256) srw[i] = rw[i];
    __syncthreads();

    int warp = tid >> 5, lane = tid & 31;
    int token = blockIdx.x * 8 + warp;
    const float* xr = x + (size_t)token * C_DIM;

    float acc[E_NUM];
#pragma unroll
    for (int e = 0; e < E_NUM; e++) acc[e] = 0.f;
    for (int c = lane; c < C_DIM; c += 32) {
        float xv = xr[c];
#pragma unroll
        for (int e = 0; e < E_NUM; e++) acc[e] += xv * srw[e * C_DIM + c];
    }
#pragma unroll
    for (int e = 0; e < E_NUM; e++) {
#pragma unroll
        for (int o = 16; o; o >>= 1)
            acc[e] += __shfl_xor_sync(0xffffffffu, acc[e], o);
    }
    if (lane == 0) {
        int e0 = 0; float v0 = acc[0];
#pragma unroll
        for (int e = 1; e < E_NUM; e++)
            if (acc[e] > v0) { v0 = acc[e]; e0 = e; }
        int e1 = -1; float v1 = -INFINITY;
#pragma unroll
        for (int e = 0; e < E_NUM; e++)
            if (e != e0 && acc[e] > v1) { v1 = acc[e]; e1 = e; }
        float t  = expf(v1 - v0);
        float p0 = 1.f / (1.f + t);
        float p1 = t / (1.f + t);
        g_tok_e[token * 2 + 0] = e0;
        g_tok_e[token * 2 + 1] = e1;
        g_tok_p[token * 2 + 0] = p0;
        g_tok_p[token * 2 + 1] = p1;
        atomicAdd(&g_counts[e0], 1);
        atomicAdd(&g_counts[e1], 1);
    }
}

__global__ void offsets_kernel() {
    int s = 0;
    for (int e = 0; e < E_NUM; e++) {
        g_base[e]   = s;
        g_cursor[e] = s;
        s += g_counts[e];
    }
}

__global__ void scatter_kernel() {
    int n = blockIdx.x * blockDim.x + threadIdx.x;
    if (n >= N_TOK) return;
#pragma unroll
    for (int k = 0; k < 2; k++) {
        int e = g_tok_e[n * 2 + k];
        int slot = atomicAdd(&g_cursor[e], 1);
        g_slot_tok[slot] = n;
        g_slot_p[slot]   = g_tok_p[n * 2 + k];
    }
}

// ---- splits: device symbols referenced directly ----
__device__ __forceinline__ void split_store(const float* __restrict__ src,
                                            __nv_bfloat16* dh, __nv_bfloat16* dl,
                                            size_t i) {
    float4 v = *(const float4*)(src + i);
    __nv_bfloat16 h0, l0, h1, l1, h2, l2, h3, l3;
    split2(v.x, h0, l0); split2(v.y, h1, l1);
    split2(v.z, h2, l2); split2(v.w, h3, l3);
    __nv_bfloat162* ph = (__nv_bfloat162*)(dh + i);
    __nv_bfloat162* pl = (__nv_bfloat162*)(dl + i);
    ph[0] = __nv_bfloat162(h0, h1); ph[1] = __nv_bfloat162(h2, h3);
    pl[0] = __nv_bfloat162(l0, l1); pl[1] = __nv_bfloat162(l2, l3);
}

__global__ void split_x_kernel(const float* __restrict__ x) {
    size_t i = (size_t)(blockIdx.x * 256 + threadIdx.x) * 4;
    split_store(x, g_xh, g_xl, i);
}
__global__ void split_w1_kernel(const float* __restrict__ w1) {
    size_t i = (size_t)(blockIdx.x * 256 + threadIdx.x) * 4;
    split_store(w1, g_w1h, g_w1l, i);
}
__global__ void split_w2_kernel(const float* __restrict__ w2) {
    size_t i = (size_t)(blockIdx.x * 256 + threadIdx.x) * 4;
    split_store(w2, g_w2h, g_w2l, i);
}

// ---------------- GEMM1: H = relu(x[tok] @ w1[e])^2 (cp.async double-buffered) ----------------
__global__ void __launch_bounds__(256, 2)
gemm1_kernel() {
    const int e  = blockIdx.z;
    const int ne = g_counts[e];
    const int m0 = blockIdx.y * BM;
    if (m0 >= ne) return;
    const int base = g_base[e];
    const int n0   = blockIdx.x * BN;

    __shared__ __align__(16) __nv_bfloat16 sAh[2][BM][ASTR];
    __shared__ __align__(16) __nv_bfloat16 sAl[2][BM][ASTR];
    __shared__ __align__(16) __nv_bfloat16 sBh[2][BK][BSTR];
    __shared__ __align__(16) __nv_bfloat16 sBl[2][BK][BSTR];
    __shared__ int stok[BM];

    const int t = threadIdx.x;
    const int wid = t >> 5, lane = t & 31;
    const int g = lane >> 2, tg = lane & 3;

    if (t < BM) {
        int m = m0 + t;
        stok[t] = (m < ne) ? g_slot_tok[base + m] : 0;
    }
    __syncthreads();

    const int ar = t >> 1, ah = (t & 1) * 8;
    const int br = t >> 4, bc = (t & 15) * 8;

    const size_t arow = (size_t)stok[ar];
    const __nv_bfloat16* agh = g_xh + arow * KTOT + ah;
    const __nv_bfloat16* agl = g_xl + arow * KTOT + ah;
    const __nv_bfloat16* bgh = g_w1h + ((size_t)e << 20) + (size_t)br * KTOT + n0 + bc;
    const __nv_bfloat16* bgl = g_w1l + ((size_t)e << 20) + (size_t)br * KTOT + n0 + bc;

    // cp.async smem destinations (stage 0)
    const uint32_t dAh = (uint32_t)__cvta_generic_to_shared(&sAh[0][ar][ah]);
    const uint32_t dAl = (uint32_t)__cvta_generic_to_shared(&sAl[0][ar][ah]);
    const uint32_t dBh = (uint32_t)__cvta_generic_to_shared(&sBh[0][br][bc]);
    const uint32_t dBl = (uint32_t)__cvta_generic_to_shared(&sBl[0][br][bc]);

    const int wm = (wid >> 2) * 64;
    const int wn = (wid & 3) * 32;

    const int lr = lane & 15;
    const int lc = (lane >> 4) * 8;
    uint32_t aAh[4], aAl[4];
#pragma unroll
    for (int mt = 0; mt < 4; mt++) {
        aAh[mt] = (uint32_t)__cvta_generic_to_shared(&sAh[0][wm + mt * 16 + lr][lc]);
        aAl[mt] = (uint32_t)__cvta_generic_to_shared(&sAl[0][wm + mt * 16 + lr][lc]);
    }
    uint32_t aBh[4], aBl[4];
#pragma unroll
    for (int nt = 0; nt < 4; nt++) {
        aBh[nt] = (uint32_t)__cvta_generic_to_shared(&sBh[0][lr][wn + nt * 8]);
        aBl[nt] = (uint32_t)__cvta_generic_to_shared(&sBl[0][lr][wn + nt * 8]);
    }

    float acc[4][4][4];
#pragma unroll
    for (int i = 0; i < 4; i++)
#pragma unroll
        for (int j = 0; j < 4; j++)
#pragma unroll
            for (int q = 0; q < 4; q++) acc[i][j][q] = 0.f;

    // prologue: chunk 0 -> stage 0
    cpa16(dAh, agh);
    cpa16(dAl, agl);
    cpa16(dBh, bgh);
    cpa16(dBl, bgl);
    cp_commit();

    for (int c = 0; c < NCHUNK; c++) {
        const uint32_t ao = (c & 1) * A_STAGE_B;
        const uint32_t bo = (c & 1) * B_STAGE_B;

        cp_wait0();          // chunk c landed (only group in flight)
        __syncthreads();     // all warps done reading the other stage (chunk c-1)

        if (c + 1 < NCHUNK) {  // fill other stage; completes under the MMAs below
            const uint32_t ao2 = ((c + 1) & 1) * A_STAGE_B;
            const uint32_t bo2 = ((c + 1) & 1) * B_STAGE_B;
            cpa16(dAh + ao2, agh + (c + 1) * BK);
            cpa16(dAl + ao2, agl + (c + 1) * BK);
            cpa16(dBh + bo2, bgh + (size_t)(c + 1) * BK * KTOT);
            cpa16(dBl + bo2, bgl + (size_t)(c + 1) * BK * KTOT);
            cp_commit();
        }

        // B fragments once per chunk
        uint32_t fbh[4][2], fbl[4][2];
#pragma unroll
        for (int nt = 0; nt < 4; nt++) {
            ldsm_x2t(fbh[nt], aBh[nt] + bo);
            ldsm_x2t(fbl[nt], aBl[nt] + bo);
        }
        // stream A fragments (mt outer keeps live regs low)
#pragma unroll
        for (int mt = 0; mt < 4; mt++) {
            uint32_t fah[4], fal[4];
            ldsm_x4(fah, aAh[mt] + ao);
            ldsm_x4(fal, aAl[mt] + ao);
#pragma unroll
            for (int nt = 0; nt < 4; nt++) {
                mma_bf16(acc[mt][nt], fah, fbh[nt]);
                mma_bf16(acc[mt][nt], fah, fbl[nt]);
                mma_bf16(acc[mt][nt], fal, fbh[nt]);
            }
        }
    }

#pragma unroll
    for (int mt = 0; mt < 4; mt++) {
#pragma unroll
        for (int half = 0; half < 2; half++) {
            const int mrow = wm + mt * 16 + g + half * 8;
            if (m0 + mrow < ne) {
                size_t roff = (size_t)(base + m0 + mrow) * KTOT + n0 + wn + tg * 2;
#pragma unroll
                for (int nt = 0; nt < 4; nt++) {
                    float q0 = fmaxf(acc[mt][nt][half * 2 + 0], 0.f);
                    float q1 = fmaxf(acc[mt][nt][half * 2 + 1], 0.f);
                    float h0 = q0 * q0, h1 = q1 * q1;
                    __nv_bfloat16 a0, b0, a1, b1;
                    split2(h0, a0, b0);
                    split2(h1, a1, b1);
                    *(__nv_bfloat162*)(g_hh + roff + nt * 8) = __nv_bfloat162(a0, a1);
                    *(__nv_bfloat162*)(g_hl + roff + nt * 8) = __nv_bfloat162(b0, b1);
                }
            }
        }
    }
}

// ---------------- GEMM2: out[tok] += p * (H @ w2[e]) (cp.async double-buffered) ----------------
__global__ void __launch_bounds__(256, 2)
gemm2_kernel(float* __restrict__ out) {
    const int e  = blockIdx.z;
    const int ne = g_counts[e];
    const int m0 = blockIdx.y * BM;
    if (m0 >= ne) return;
    const int base = g_base[e];
    const int n0   = blockIdx.x * BN;

    __shared__ __align__(16) __nv_bfloat16 sAh[2][BM][ASTR];
    __shared__ __align__(16) __nv_bfloat16 sAl[2][BM][ASTR];
    __shared__ __align__(16) __nv_bfloat16 sBh[2][BK][BSTR];
    __shared__ __align__(16) __nv_bfloat16 sBl[2][BK][BSTR];
    __shared__ int   stok[BM];
    __shared__ float sp[BM];

    const int t = threadIdx.x;
    const int wid = t >> 5, lane = t & 31;
    const int g = lane >> 2, tg = lane & 3;

    if (t < BM) {
        int m = m0 + t;
        if (m < ne) {
            stok[t] = g_slot_tok[base + m];
            sp[t]   = g_slot_p[base + m];
        } else {
            stok[t] = 0;
            sp[t]   = 0.f;
        }
    }
    __syncthreads();

    const int ar = t >> 1, ah = (t & 1) * 8;
    const int br = t >> 4, bc = (t & 15) * 8;

    const size_t arow = (size_t)(base + m0 + ar);
    const __nv_bfloat16* agh = g_hh + arow * KTOT + ah;
    const __nv_bfloat16* agl = g_hl + arow * KTOT + ah;
    const __nv_bfloat16* bgh = g_w2h + ((size_t)e << 20) + (size_t)br * KTOT + n0 + bc;
    const __nv_bfloat16* bgl = g_w2l + ((size_t)e << 20) + (size_t)br * KTOT + n0 + bc;

    const uint32_t dAh = (uint32_t)__cvta_generic_to_shared(&sAh[0][ar][ah]);
    const uint32_t dAl = (uint32_t)__cvta_generic_to_shared(&sAl[0][ar][ah]);
    const uint32_t dBh = (uint32_t)__cvta_generic_to_shared(&sBh[0][br][bc]);
    const uint32_t dBl = (uint32_t)__cvta_generic_to_shared(&sBl[0][br][bc]);

    const int wm = (wid >> 2) * 64;
    const int wn = (wid & 3) * 32;

    const int lr = lane & 15;
    const int lc = (lane >> 4) * 8;
    uint32_t aAh[4], aAl[4];
#pragma unroll
    for (int mt = 0; mt < 4; mt++) {
        aAh[mt] = (uint32_t)__cvta_generic_to_shared(&sAh[0][wm + mt * 16 + lr][lc]);
        aAl[mt] = (uint32_t)__cvta_generic_to_shared(&sAl[0][wm + mt * 16 + lr][lc]);
    }
    uint32_t aBh[4], aBl[4];
#pragma unroll
    for (int nt = 0; nt < 4; nt++) {
        aBh[nt] = (uint32_t)__cvta_generic_to_shared(&sBh[0][lr][wn + nt * 8]);
        aBl[nt] = (uint32_t)__cvta_generic_to_shared(&sBl[0][lr][wn + nt * 8]);
    }

    float acc[4][4][4];
#pragma unroll
    for (int i = 0; i < 4; i++)
#pragma unroll
        for (int j = 0; j < 4; j++)
#pragma unroll
            for (int q = 0; q < 4; q++) acc[i][j][q] = 0.f;

    cpa16(dAh, agh);
    cpa16(dAl, agl);
    cpa16(dBh, bgh);
    cpa16(dBl, bgl);
    cp_commit();

    for (int c = 0; c < NCHUNK; c++) {
        const uint32_t ao = (c & 1) * A_STAGE_B;
        const uint32_t bo = (c & 1) * B_STAGE_B;

        cp_wait0();
        __syncthreads();

        if (c + 1 < NCHUNK) {
            const uint32_t ao2 = ((c + 1) & 1) * A_STAGE_B;
            const uint32_t bo2 = ((c + 1) & 1) * B_STAGE_B;
            cpa16(dAh + ao2, agh + (c + 1) * BK);
            cpa16(dAl + ao2, agl + (c + 1) * BK);
            cpa16(dBh + bo2, bgh + (size_t)(c + 1) * BK * KTOT);
            cpa16(dBl + bo2, bgl + (size_t)(c + 1) * BK * KTOT);
            cp_commit();
        }

        uint32_t fbh[4][2], fbl[4][2];
#pragma unroll
        for (int nt = 0; nt < 4; nt++) {
            ldsm_x2t(fbh[nt], aBh[nt] + bo);
            ldsm_x2t(fbl[nt], aBl[nt] + bo);
        }
#pragma unroll
        for (int mt = 0; mt < 4; mt++) {
            uint32_t fah[4], fal[4];
            ldsm_x4(fah, aAh[mt] + ao);
            ldsm_x4(fal, aAl[mt] + ao);
#pragma unroll
            for (int nt = 0; nt < 4; nt++) {
                mma_bf16(acc[mt][nt], fah, fbh[nt]);
                mma_bf16(acc[mt][nt], fah, fbl[nt]);
                mma_bf16(acc[mt][nt], fal, fbh[nt]);
            }
        }
    }

#pragma unroll
    for (int mt = 0; mt < 4; mt++) {
#pragma unroll
        for (int half = 0; half < 2; half++) {
            const int mrow = wm + mt * 16 + g + half * 8;
            if (m0 + mrow < ne) {
                const int token = stok[mrow];
                const float p   = sp[mrow];
                float* op = out + (size_t)token * C_DIM + n0 + wn + tg * 2;
#pragma unroll
                for (int nt = 0; nt < 4; nt++) {
                    atomicAdd(op + nt * 8 + 0, p * acc[mt][nt][half * 2 + 0]);
                    atomicAdd(op + nt * 8 + 1, p * acc[mt][nt][half * 2 + 1]);
                }
            }
        }
    }
}

// ---------------- host launch ----------------
extern "C" void kernel_launch(void* const* d_in, const int* in_sizes, int n_in,
                              void* d_out, int out_size) {
    const float* x  = (const float*)d_in[0];
    const float* rw = (const float*)d_in[1];
    const float* w1 = (const float*)d_in[2];
    const float* w2 = (const float*)d_in[3];
    float* out = (float*)d_out;

    cudaMemsetAsync(out, 0, (size_t)out_size * sizeof(float));
    init_kernel<<<1, 32>>>();
    router_kernel<<<N_TOK / 8, 256>>>(x, rw);
    offsets_kernel<<<1, 1>>>();
    scatter_kernel<<<N_TOK / 256, 256>>>();

    split_x_kernel<<<(N_TOK * C_DIM / 4) / 256, 256>>>(x);
    split_w1_kernel<<<(E_NUM * C_DIM * D_DIM / 4) / 256, 256>>>(w1);
    split_w2_kernel<<<(E_NUM * D_DIM * C_DIM / 4) / 256, 256>>>(w2);

    dim3 g1(D_DIM / BN, 64, E_NUM);
    gemm1_kernel<<<g1, 256>>>();
    dim3 g2(C_DIM / BN, 64, E_NUM);
    gemm2_kernel<<<g2, 256>>>(out);
}